// round 11
// baseline (speedup 1.0000x reference)
#include <cuda_runtime.h>
#include <cstdint>

// out[b,k,oc,x] = sum_ci W[k,oc,ci]*in[b,ci,k,x] + bias[k,oc]
// in: [4096,128,9,9]  w: [9,128,128]  bias: [9,128]  out: [4096,9,128,9] (f32)
//
// R11: W evicted from smem. Prep kernel packs per-warp A-fragments (tf32-rna)
// into g_W2; main kernel fetches A via one coalesced LDG.128 per kstep (L1-resident).
// smem holds only X stages (4 x quarter-K x 72n = 36.9 KB) -> 3 CTAs/SM, 24 warps.
// X via cp.async (raw f32 bits -> tf32 truncation in MMA), wait_group 2, sync/quarter.

#define KK     9
#define CIN    128
#define COUT   128
#define NB     8
#define TILES  4
#define NTHR   256
#define NBUF   4
#define NSTEP  (NBUF * TILES)   // 16 quarters per CTA

#define SXS 72                  // stage stride: B-frag banks (8t+8nt+g) perfect
#define XQ_WORDS (32 * SXS)     // 2304 words per quarter (9216 B)
#define SMEM_WORDS (NBUF * XQ_WORDS)   // 9216 words = 36864 B -> 3 CTAs/SM

// packed A-frags: [k][wid(8)][ks(16)][lane(32)][4] tf32 bits
__device__ uint32_t g_W2[KK * 8 * 16 * 32 * 4];

__device__ __forceinline__ uint32_t f2tf32(float f) {
    uint32_t u;
    asm("cvt.rna.tf32.f32 %0, %1;" : "=r"(u) : "f"(f));
    return u;
}
__device__ __forceinline__ uint32_t smem_u32(const void* p) {
    uint32_t a;
    asm("{ .reg .u64 t; cvta.to.shared.u64 t, %1; cvt.u32.u64 %0, t; }" : "=r"(a) : "l"(p));
    return a;
}
__device__ __forceinline__ void cp4(uint32_t dst, const float* src) {
    asm volatile("cp.async.ca.shared.global [%0], [%1], 4;" :: "r"(dst), "l"(src));
}
__device__ __forceinline__ void mma_tf32(float* d, const uint32_t* a, const uint32_t* b) {
    asm volatile(
        "mma.sync.aligned.m16n8k8.row.col.f32.tf32.tf32.f32 "
        "{%0,%1,%2,%3}, {%4,%5,%6,%7}, {%8,%9}, {%0,%1,%2,%3};"
        : "+f"(d[0]), "+f"(d[1]), "+f"(d[2]), "+f"(d[3])
        : "r"(a[0]), "r"(a[1]), "r"(a[2]), "r"(a[3]), "r"(b[0]), "r"(b[1]));
}

// ---- prep: w[9][128][128] f32 -> g_W2 packed tf32 A-frags ----
__global__ void prep_w_kernel(const float* __restrict__ w) {
    int idx = blockIdx.x * 256 + threadIdx.x;      // 0..147455
    int j    = idx & 3;
    int lane = (idx >> 2) & 31;
    int ks   = (idx >> 7) & 15;
    int wid  = (idx >> 11) & 7;
    int k    = idx >> 14;
    if (k >= KK) return;
    int g = lane >> 2, tl = lane & 3;
    int oc = wid * 16 + g + (j & 1) * 8;
    int ci = ks * 8 + tl + ((j >> 1) & 1) * 4;
    g_W2[idx] = f2tf32(w[(k * COUT + oc) * CIN + ci]);
}

__global__ void __launch_bounds__(NTHR, 3)
gather_vertical_r11(const float* __restrict__ in,
                    const float* __restrict__ bias,
                    float* __restrict__ out)
{
    __shared__ uint32_t sX[SMEM_WORDS];            // 4 stages [32 ci][72 n]

    const int tid = threadIdx.x;
    const int k   = blockIdx.x;
    const int yid = blockIdx.y;
    const int bbase = yid * TILES * NB;

    // ---- per-thread cp.async mapping: 1 row (bl,ci_l), 9 contiguous x ----
    const int pbl = tid >> 5;                      // 0..7  (batch within tile)
    const int pci = tid & 31;                      // 0..31 (ci within quarter)
    const uint32_t sx_base = smem_u32(sX);
    const uint32_t sdst0 = sx_base + (pci * SXS + pbl * 9) * 4;
    const float* src = in + ((size_t)(bbase + pbl) * CIN + pci) * 81 + (size_t)k * 9;
    // per (tile t, quarter qi): gsrc = src + t*NB*CIN*81 + qi*32*81

    // ---- prologue: stages 0..2 (tile 0, quarters 0..2) ----
    #pragma unroll
    for (int s = 0; s < 3; s++) {
        const float* st = src + s * 32 * 81;
        const uint32_t db = sdst0 + s * (XQ_WORDS * 4);
        #pragma unroll
        for (int x = 0; x < 9; x++) cp4(db + 4 * x, st + x);
        asm volatile("cp.async.commit_group;" ::: "memory");
    }

    // ---- consumer identity ----
    const int wid  = tid >> 5, lane = tid & 31;
    const int g    = lane >> 2, tl = lane & 3;
    const int r0   = wid * 16 + g, r1 = r0 + 8;
    const float bv0 = bias[k * COUT + r0];
    const float bv1 = bias[k * COUT + r1];

    // packed A pointer: one uint4 per kstep
    const uint4* wp = reinterpret_cast<const uint4*>(g_W2)
                      + ((size_t)(k * 8 + wid) * 16) * 32 + lane;

    float d[9][4];

    for (int s = 0; s < NSTEP; s++) {
        const int qi = s & 3;

        if (qi == 0) {
            #pragma unroll
            for (int nt = 0; nt < 9; nt++)
                #pragma unroll
                for (int j = 0; j < 4; j++) d[nt][j] = 0.0f;
        }

        asm volatile("cp.async.wait_group 2;" ::: "memory");   // stage s arrived
        __syncthreads();

        // issue stage s+3 into buffer (s+3)&3 (freed by the sync above)
        if (s + 3 < NSTEP) {
            const int sn = s + 3, tn = sn >> 2, qn = sn & 3;
            const float* st = src + (size_t)(tn * NB) * (CIN * 81) + qn * 32 * 81;
            const uint32_t db = sdst0 + qn * (XQ_WORDS * 4);
            #pragma unroll
            for (int x = 0; x < 9; x++) cp4(db + 4 * x, st + x);
        }
        asm volatile("cp.async.commit_group;" ::: "memory");   // possibly empty group

        // ---- MMA on stage qi: 4 k-steps, A from g_W2 (L1), B from smem ----
        {
            const uint32_t* pb = sX + qi * XQ_WORDS + tl * SXS + g;
            #pragma unroll
            for (int kk2 = 0; kk2 < 4; kk2++) {
                const int ks = qi * 4 + kk2;
                uint4 av = wp[ks * 32];
                uint32_t a[4] = {av.x, av.y, av.z, av.w};

                uint32_t b[9][2];
                #pragma unroll
                for (int nt = 0; nt < 9; nt++) {
                    b[nt][0] = pb[nt * 8];
                    b[nt][1] = pb[4 * SXS + nt * 8];
                }
                #pragma unroll
                for (int nt = 0; nt < 9; nt++)
                    mma_tf32(d[nt], a, b[nt]);

                pb += 8 * SXS;
            }
        }

        // ---- tile boundary: epilogue (direct STG) ----
        if (qi == 3) {
            const int t = s >> 2;
            float* ob = out + ((size_t)(bbase + t * NB) * 9 + k) * 1152;
            #pragma unroll
            for (int nt = 0; nt < 9; nt++) {
                int n   = nt * 8 + 2 * tl;
                int b0q = n / 9,       x0 = n - 9 * b0q;
                int b1q = (n + 1) / 9, x1 = (n + 1) - 9 * b1q;
                float* c0 = ob + (size_t)b0q * 10368;
                float* c1 = ob + (size_t)b1q * 10368;
                c0[r0 * 9 + x0] = d[nt][0] + bv0;
                c1[r0 * 9 + x1] = d[nt][1] + bv0;
                c0[r1 * 9 + x0] = d[nt][2] + bv1;
                c1[r1 * 9 + x1] = d[nt][3] + bv1;
            }
        }
    }
}

extern "C" void kernel_launch(void* const* d_in, const int* in_sizes, int n_in,
                              void* d_out, int out_size)
{
    const float* in   = (const float*)d_in[0];
    const float* w    = (const float*)d_in[1];
    const float* bias = (const float*)d_in[2];
    float* out        = (float*)d_out;

    int B = in_sizes[0] / (CIN * 81);        // 4096

    prep_w_kernel<<<(KK * 8 * 16 * 32 * 4 + 255) / 256, 256>>>(w);

    dim3 grid(KK, B / (NB * TILES));         // (9, 128)
    gather_vertical_r11<<<grid, NTHR>>>(in, bias, out);
}

// round 12
// speedup vs baseline: 1.3088x; 1.3088x over previous
#include <cuda_runtime.h>
#include <cstdint>

// out[b,k,oc,x] = sum_ci W[k,oc,ci]*in[b,ci,k,x] + bias[k,oc]
// in: [4096,128,9,9]  w: [9,128,128]  bias: [9,128]  out: [4096,9,128,9] (f32)
//
// R12: all-consumer cp.async pipeline, 12 warps as 4(M) x 3(N).
// Warp tile 32oc x 24n: 2 m-frags x 3 n-frags -> B-LDS per HMMA = 1.0 (was 2.0).
// A-frags packed by prep kernel into g_W2 (tf32-rna), fetched as 2 x LDG.128/kstep.
// X via cp.async raw f32 (tf32 truncation), 4 quarter-K stages, wait_group 2.

#define KK     9
#define CIN    128
#define COUT   128
#define NB     8
#define TILES  4
#define NTHR   384
#define NBUF   4
#define NSTEP  (NBUF * TILES)   // 16 quarters per CTA

#define SXS 72                  // stage stride: B-frag banks (tl*24+g) perfect
#define XQ_WORDS (32 * SXS)     // 2304 words per quarter (9216 B)
#define SMEM_WORDS (NBUF * XQ_WORDS)   // 9216 words = 36864 B (static)

// packed A-frags: [k][wm(4)][ks(16)][mf(2)][lane(32)][4] tf32 bits
#define W2_WORDS (KK * 4 * 16 * 2 * 32 * 4)   // 147456
__device__ uint32_t g_W2[W2_WORDS];

__device__ __forceinline__ uint32_t f2tf32(float f) {
    uint32_t u;
    asm("cvt.rna.tf32.f32 %0, %1;" : "=r"(u) : "f"(f));
    return u;
}
__device__ __forceinline__ uint32_t smem_u32(const void* p) {
    uint32_t a;
    asm("{ .reg .u64 t; cvta.to.shared.u64 t, %1; cvt.u32.u64 %0, t; }" : "=r"(a) : "l"(p));
    return a;
}
__device__ __forceinline__ void cp4(uint32_t dst, const float* src) {
    asm volatile("cp.async.ca.shared.global [%0], [%1], 4;" :: "r"(dst), "l"(src));
}
__device__ __forceinline__ void mma_tf32(float* d, const uint32_t* a, const uint32_t* b) {
    asm volatile(
        "mma.sync.aligned.m16n8k8.row.col.f32.tf32.tf32.f32 "
        "{%0,%1,%2,%3}, {%4,%5,%6,%7}, {%8,%9}, {%0,%1,%2,%3};"
        : "+f"(d[0]), "+f"(d[1]), "+f"(d[2]), "+f"(d[3])
        : "r"(a[0]), "r"(a[1]), "r"(a[2]), "r"(a[3]), "r"(b[0]), "r"(b[1]));
}

// ---- prep: w[9][128][128] f32 -> g_W2 packed tf32 A-frags ----
__global__ void prep_w_kernel(const float* __restrict__ w) {
    int idx = blockIdx.x * 256 + threadIdx.x;      // 0..147455
    if (idx >= W2_WORDS) return;
    int j    = idx & 3;
    int lane = (idx >> 2) & 31;
    int mf   = (idx >> 7) & 1;
    int ks   = (idx >> 8) & 15;
    int wm   = (idx >> 12) & 3;
    int k    = idx >> 14;
    int g = lane >> 2, tl = lane & 3;
    int oc = wm * 32 + mf * 16 + g + (j & 1) * 8;
    int ci = ks * 8 + tl + ((j >> 1) & 1) * 4;
    g_W2[idx] = f2tf32(w[(k * COUT + oc) * CIN + ci]);
}

__global__ void __launch_bounds__(NTHR, 2)
gather_vertical_r12(const float* __restrict__ in,
                    const float* __restrict__ bias,
                    float* __restrict__ out)
{
    __shared__ uint32_t sX[SMEM_WORDS];            // 4 stages [32 ci][72 n]

    const int tid = threadIdx.x;
    const int k   = blockIdx.x;
    const int yid = blockIdx.y;
    const int bbase = yid * TILES * NB;

    // ---- per-thread cp.async offsets (6 words per stage), loop-invariant ----
    const float* src = in + (size_t)bbase * (CIN * 81) + (size_t)k * 9;
    const uint32_t sx_base = smem_u32(sX);
    int goff[6], soff[6];
    #pragma unroll
    for (int j = 0; j < 6; j++) {
        int e  = tid + NTHR * j;      // 0..2303
        int q  = e / 9;               // bl*32 + ci_local
        int x  = e - 9 * q;
        int bl = q >> 5;
        int ci = q & 31;
        goff[j] = (bl * CIN + ci) * 81 + x;
        soff[j] = (ci * SXS + bl * 9 + x) * 4;
    }

    // ---- prologue: stages 0..2 (tile 0, quarters 0..2) ----
    #pragma unroll
    for (int s = 0; s < 3; s++) {
        const float* st = src + s * 32 * 81;
        const uint32_t db = sx_base + s * (XQ_WORDS * 4);
        #pragma unroll
        for (int j = 0; j < 6; j++) cp4(db + soff[j], st + goff[j]);
        asm volatile("cp.async.commit_group;" ::: "memory");
    }

    // ---- consumer identity: 12 warps = 4(M) x 3(N) ----
    const int wid  = tid >> 5, lane = tid & 31;
    const int g    = lane >> 2, tl = lane & 3;
    const int wm   = wid & 3;          // 0..3 -> oc base wm*32
    const int wn   = wid >> 2;         // 0..2 -> n  base wn*24
    const int n0   = wn * 24;
    const int rA   = wm * 32 + g;      // rows rA, rA+8 (mf0), rA+16, rA+24 (mf1)
    float bv[4];
    #pragma unroll
    for (int m = 0; m < 4; m++) bv[m] = bias[k * COUT + rA + m * 8];

    // packed A base: uint4 layout [k][wm][ks][mf][lane], 1024 uint4 per (k,wm)
    const uint4* wpbase = reinterpret_cast<const uint4*>(g_W2)
                          + (size_t)(k * 4 + wm) * 1024 + lane;

    float d[2][3][4];

    for (int s = 0; s < NSTEP; s++) {
        const int qi = s & 3;

        if (qi == 0) {
            #pragma unroll
            for (int mf = 0; mf < 2; mf++)
                #pragma unroll
                for (int nt = 0; nt < 3; nt++)
                    #pragma unroll
                    for (int j = 0; j < 4; j++) d[mf][nt][j] = 0.0f;
        }

        asm volatile("cp.async.wait_group 2;" ::: "memory");   // stage s arrived
        __syncthreads();

        // issue stage s+3 into buffer (s+3)&3 (freed by the sync above)
        if (s + 3 < NSTEP) {
            const int sn = s + 3, tn = sn >> 2, qn = sn & 3;
            const float* st = src + (size_t)(tn * NB) * (CIN * 81) + qn * 32 * 81;
            const uint32_t db = sx_base + qn * (XQ_WORDS * 4);
            #pragma unroll
            for (int j = 0; j < 6; j++) cp4(db + soff[j], st + goff[j]);
        }
        asm volatile("cp.async.commit_group;" ::: "memory");   // possibly empty group

        // ---- MMA on stage qi: 4 k-steps; A: 2 LDG.128, B: 6 LDS, 6 HMMA ----
        {
            const uint32_t* pb = sX + qi * XQ_WORDS + tl * SXS + g + n0;
            #pragma unroll
            for (int kk2 = 0; kk2 < 4; kk2++) {
                const int ks = qi * 4 + kk2;
                uint4 av0 = wpbase[ks * 64];          // mf0
                uint4 av1 = wpbase[ks * 64 + 32];     // mf1
                uint32_t a0[4] = {av0.x, av0.y, av0.z, av0.w};
                uint32_t a1[4] = {av1.x, av1.y, av1.z, av1.w};

                uint32_t b[3][2];
                #pragma unroll
                for (int nt = 0; nt < 3; nt++) {
                    b[nt][0] = pb[nt * 8];
                    b[nt][1] = pb[4 * SXS + nt * 8];
                }
                #pragma unroll
                for (int nt = 0; nt < 3; nt++) {
                    mma_tf32(d[0][nt], a0, b[nt]);
                    mma_tf32(d[1][nt], a1, b[nt]);
                }
                pb += 8 * SXS;
            }
        }

        // ---- tile boundary: epilogue (direct STG) ----
        if (qi == 3) {
            const int t = s >> 2;
            float* ob = out + ((size_t)(bbase + t * NB) * 9 + k) * 1152;
            #pragma unroll
            for (int mf = 0; mf < 2; mf++) {
                int r0 = rA + mf * 16, r1 = r0 + 8;
                float bv0 = bv[mf * 2], bv1 = bv[mf * 2 + 1];
                #pragma unroll
                for (int nt = 0; nt < 3; nt++) {
                    int n   = n0 + nt * 8 + 2 * tl;
                    int b0q = n / 9,       x0 = n - 9 * b0q;
                    int b1q = (n + 1) / 9, x1 = (n + 1) - 9 * b1q;
                    float* c0 = ob + (size_t)b0q * 10368;
                    float* c1 = ob + (size_t)b1q * 10368;
                    c0[r0 * 9 + x0] = d[mf][nt][0] + bv0;
                    c1[r0 * 9 + x1] = d[mf][nt][1] + bv0;
                    c0[r1 * 9 + x0] = d[mf][nt][2] + bv1;
                    c1[r1 * 9 + x1] = d[mf][nt][3] + bv1;
                }
            }
        }
    }
}

extern "C" void kernel_launch(void* const* d_in, const int* in_sizes, int n_in,
                              void* d_out, int out_size)
{
    const float* in   = (const float*)d_in[0];
    const float* w    = (const float*)d_in[1];
    const float* bias = (const float*)d_in[2];
    float* out        = (float*)d_out;

    int B = in_sizes[0] / (CIN * 81);        // 4096

    prep_w_kernel<<<(W2_WORDS + 255) / 256, 256>>>(w);

    dim3 grid(KK, B / (NB * TILES));         // (9, 128)
    gather_vertical_r12<<<grid, NTHR>>>(in, bias, out);
}